// round 2
// baseline (speedup 1.0000x reference)
#include <cuda_runtime.h>
#include <math.h>

#define BB 16
#define NNODE 1024
#define FF 512

// Scratch (allocation-free rule: __device__ globals)
__device__ float g_r[BB * NNODE];                 // rsqrt(colsum)
__device__ float g_h[BB * NNODE * FF];            // Hs = r .* (X@W)
__device__ float g_x[BB * NNODE * FF];            // layer activations

// -------------------------------------------------------------------------
// colsum[b,j] = sum_i adj[b,i,j];  r = colsum > 0 ? rsqrt(colsum) : 0
// blockDim (64,4): 64 columns per block, 4 partial sums per column.
// -------------------------------------------------------------------------
__global__ void colsum_kernel(const float* __restrict__ adj,
                              float* __restrict__ r) {
    __shared__ float red[4][64];
    const int jj = threadIdx.x;       // 0..63
    const int ii = threadIdx.y;       // 0..3
    const int col = blockIdx.x * 64 + jj;   // flat b*N + j (64 | N so same b)
    const int b = col / NNODE;
    const int j = col % NNODE;
    const float* a = adj + (size_t)b * NNODE * NNODE + j;
    float s = 0.f;
#pragma unroll 8
    for (int i = ii; i < NNODE; i += 4)
        s += a[(size_t)i * NNODE];
    red[ii][jj] = s;
    __syncthreads();
    if (ii == 0) {
        float t = red[0][jj] + red[1][jj] + red[2][jj] + red[3][jj];
        r[col] = (t > 0.f) ? rsqrtf(t) : 0.f;
    }
}

// -------------------------------------------------------------------------
// Feature GEMM:  out[m,f] = r[m] * sum_k X[m,k] * W[k,f]
// M = BB*NNODE (16384), K = FF, N = FF. 128x128x8 tile, 8x8/thread.
// -------------------------------------------------------------------------
__global__ void __launch_bounds__(256) xw_gemm(
    const float* __restrict__ X, const float* __restrict__ W,
    const float* __restrict__ r, float* __restrict__ out) {
    __shared__ float As[8][128];
    __shared__ float Bs[8][128];
    const int tid = threadIdx.x;
    const int m0 = blockIdx.y * 128;
    const int n0 = blockIdx.x * 128;
    const int tx = tid & 15, ty = tid >> 4;

    const int aRow = tid >> 1;          // 0..127
    const int aCol = (tid & 1) * 4;     // 0 or 4
    const int bRow = tid >> 5;          // 0..7
    const int bCol = (tid & 31) * 4;    // 0..124

    float acc[8][8] = {};

    for (int k0 = 0; k0 < FF; k0 += 8) {
        float4 av = *(const float4*)&X[(size_t)(m0 + aRow) * FF + k0 + aCol];
        As[aCol + 0][aRow] = av.x;
        As[aCol + 1][aRow] = av.y;
        As[aCol + 2][aRow] = av.z;
        As[aCol + 3][aRow] = av.w;
        *(float4*)&Bs[bRow][bCol] =
            *(const float4*)&W[(size_t)(k0 + bRow) * FF + n0 + bCol];
        __syncthreads();
#pragma unroll
        for (int kk = 0; kk < 8; kk++) {
            float4 a0 = *(const float4*)&As[kk][ty * 8];
            float4 a1 = *(const float4*)&As[kk][ty * 8 + 4];
            float4 b0 = *(const float4*)&Bs[kk][tx * 8];
            float4 b1 = *(const float4*)&Bs[kk][tx * 8 + 4];
            float av8[8] = {a0.x, a0.y, a0.z, a0.w, a1.x, a1.y, a1.z, a1.w};
            float bv8[8] = {b0.x, b0.y, b0.z, b0.w, b1.x, b1.y, b1.z, b1.w};
#pragma unroll
            for (int i = 0; i < 8; i++)
#pragma unroll
                for (int j = 0; j < 8; j++)
                    acc[i][j] += av8[i] * bv8[j];
        }
        __syncthreads();
    }
#pragma unroll
    for (int i = 0; i < 8; i++) {
        const int m = m0 + ty * 8 + i;
        const float scale = r[m];
#pragma unroll
        for (int j = 0; j < 8; j += 4) {
            float4 v;
            v.x = scale * acc[i][j + 0];
            v.y = scale * acc[i][j + 1];
            v.z = scale * acc[i][j + 2];
            v.w = scale * acc[i][j + 3];
            *(float4*)&out[(size_t)m * FF + n0 + tx * 8 + j] = v;
        }
    }
}

// -------------------------------------------------------------------------
// Adjacency GEMM: out[b,i,f] = act( r[b,i]*sum_j adj[b,j,i]*H[b,j,f] + bias[f] )
// adj accessed transposed: contiguous in i -> coalesced, no SMEM transpose.
// M = NNODE, K = NNODE, N = FF per batch. Grid z = batch.
// -------------------------------------------------------------------------
__global__ void __launch_bounds__(256) adj_gemm(
    const float* __restrict__ adj, const float* __restrict__ H,
    const float* __restrict__ r, const float* __restrict__ bias,
    float* __restrict__ out, int do_relu) {
    __shared__ float As[8][128];
    __shared__ float Bs[8][128];
    const int b = blockIdx.z;
    const float* A = adj + (size_t)b * NNODE * NNODE;
    const float* Bm = H + (size_t)b * NNODE * FF;
    float* O = out + (size_t)b * NNODE * FF;
    const int tid = threadIdx.x;
    const int m0 = blockIdx.y * 128;   // i
    const int n0 = blockIdx.x * 128;   // f
    const int tx = tid & 15, ty = tid >> 4;

    const int ldRow = tid >> 5;         // 0..7  (k within tile)
    const int ldCol = (tid & 31) * 4;   // 0..124

    float acc[8][8] = {};

    for (int k0 = 0; k0 < NNODE; k0 += 8) {
        // A_eff[i][k] = adj[(k)*N + i]  -> already [k][i] layout
        *(float4*)&As[ldRow][ldCol] =
            *(const float4*)&A[(size_t)(k0 + ldRow) * NNODE + m0 + ldCol];
        *(float4*)&Bs[ldRow][ldCol] =
            *(const float4*)&Bm[(size_t)(k0 + ldRow) * FF + n0 + ldCol];
        __syncthreads();
#pragma unroll
        for (int kk = 0; kk < 8; kk++) {
            float4 a0 = *(const float4*)&As[kk][ty * 8];
            float4 a1 = *(const float4*)&As[kk][ty * 8 + 4];
            float4 b0 = *(const float4*)&Bs[kk][tx * 8];
            float4 b1 = *(const float4*)&Bs[kk][tx * 8 + 4];
            float av8[8] = {a0.x, a0.y, a0.z, a0.w, a1.x, a1.y, a1.z, a1.w};
            float bv8[8] = {b0.x, b0.y, b0.z, b0.w, b1.x, b1.y, b1.z, b1.w};
#pragma unroll
            for (int i = 0; i < 8; i++)
#pragma unroll
                for (int j = 0; j < 8; j++)
                    acc[i][j] += av8[i] * bv8[j];
        }
        __syncthreads();
    }
    const float* rb = r + b * NNODE;
#pragma unroll
    for (int i = 0; i < 8; i++) {
        const int m = m0 + ty * 8 + i;
        const float scale = rb[m];
#pragma unroll
        for (int j = 0; j < 8; j += 4) {
            const int f = n0 + tx * 8 + j;
            float4 v;
            v.x = scale * acc[i][j + 0] + bias[f + 0];
            v.y = scale * acc[i][j + 1] + bias[f + 1];
            v.z = scale * acc[i][j + 2] + bias[f + 2];
            v.w = scale * acc[i][j + 3] + bias[f + 3];
            if (do_relu) {
                v.x = fmaxf(v.x, 0.f);
                v.y = fmaxf(v.y, 0.f);
                v.z = fmaxf(v.z, 0.f);
                v.w = fmaxf(v.w, 0.f);
            }
            *(float4*)&O[(size_t)m * FF + f] = v;
        }
    }
}

extern "C" void kernel_launch(void* const* d_in, const int* in_sizes, int n_in,
                              void* d_out, int out_size) {
    const float* Xin = (const float*)d_in[0];   // batch_graph [16,1024,512]
    const float* adj = (const float*)d_in[1];   // [16,1024,1024]
    const float* W1  = (const float*)d_in[2];
    const float* b1  = (const float*)d_in[3];
    const float* W2  = (const float*)d_in[4];
    const float* b2  = (const float*)d_in[5];
    const float* W3  = (const float*)d_in[6];
    const float* b3  = (const float*)d_in[7];
    float* out = (float*)d_out;

    float *r, *h, *x;
    cudaGetSymbolAddress((void**)&r, g_r);
    cudaGetSymbolAddress((void**)&h, g_h);
    cudaGetSymbolAddress((void**)&x, g_x);

    colsum_kernel<<<BB * NNODE / 64, dim3(64, 4)>>>(adj, r);

    dim3 gA(FF / 128, BB * NNODE / 128);   // (4, 128)
    dim3 gB(FF / 128, NNODE / 128, BB);    // (4, 8, 16)

    // Layer 1
    xw_gemm<<<gA, 256>>>(Xin, W1, r, h);
    adj_gemm<<<gB, 256>>>(adj, h, r, b1, x, 1);
    // Layer 2
    xw_gemm<<<gA, 256>>>(x, W2, r, h);
    adj_gemm<<<gB, 256>>>(adj, h, r, b2, x, 1);
    // Layer 3
    xw_gemm<<<gA, 256>>>(x, W3, r, h);
    adj_gemm<<<gB, 256>>>(adj, h, r, b3, out, 0);
}

// round 5
// speedup vs baseline: 2.8283x; 2.8283x over previous
#include <cuda_runtime.h>
#include <cuda_bf16.h>
#include <stdint.h>
#include <math.h>

#define BB 16
#define NN 1024
#define FF 512

// ---------------- scratch (__device__ globals; no allocs allowed) ----------
__device__ float g_r[BB * NN];
__device__ __nv_bfloat16 g_adjT_hi[BB * NN * NN];   // [b][i][j] = adj[b][j][i]
__device__ __nv_bfloat16 g_adjT_lo[BB * NN * NN];
__device__ __nv_bfloat16 g_hst_hi[BB * FF * NN];    // HsT [b][f][j]
__device__ __nv_bfloat16 g_hst_lo[BB * FF * NN];
__device__ __nv_bfloat16 g_xb_hi[BB * NN * FF];     // activations [b][node][f]
__device__ __nv_bfloat16 g_xb_lo[BB * NN * FF];
__device__ __nv_bfloat16 g_wt_hi[3 * FF * FF];      // W^T per layer [f][k]
__device__ __nv_bfloat16 g_wt_lo[3 * FF * FF];

// ---------------- base-ISA PTX helpers (sm_80+: valid for sm_103 target) ---
__device__ __forceinline__ uint32_t smem_u32(const void* p) {
    uint32_t a;
    asm("{ .reg .u64 t; cvta.to.shared.u64 t, %1; cvt.u32.u64 %0, t; }"
        : "=r"(a) : "l"(p));
    return a;
}
__device__ __forceinline__ void cp16(uint32_t s, const void* g) {
    asm volatile("cp.async.cg.shared.global [%0], [%1], 16;" :: "r"(s), "l"(g));
}
#define CP_COMMIT() asm volatile("cp.async.commit_group;" ::: "memory")
#define CP_WAIT1() asm volatile("cp.async.wait_group 1;" ::: "memory")
#define CP_WAIT0() asm volatile("cp.async.wait_group 0;" ::: "memory")

__device__ __forceinline__ void ldsm4(uint32_t* r, uint32_t addr) {
    asm volatile("ldmatrix.sync.aligned.m8n8.x4.shared.b16 {%0,%1,%2,%3}, [%4];"
        : "=r"(r[0]), "=r"(r[1]), "=r"(r[2]), "=r"(r[3]) : "r"(addr));
}
__device__ __forceinline__ void mma_bf16(float* c, const uint32_t* a,
                                         const uint32_t* b) {
    asm volatile(
        "mma.sync.aligned.m16n8k16.row.col.f32.bf16.bf16.f32 "
        "{%0,%1,%2,%3}, {%4,%5,%6,%7}, {%8,%9}, {%0,%1,%2,%3};"
        : "+f"(c[0]), "+f"(c[1]), "+f"(c[2]), "+f"(c[3])
        : "r"(a[0]), "r"(a[1]), "r"(a[2]), "r"(a[3]), "r"(b[0]), "r"(b[1]));
}
__device__ __forceinline__ uint32_t sw128(uint32_t x) { return x ^ ((x >> 3) & 0x70); }

// SMEM layout: 4 tiles of 128 rows x 128B (AH, AL, BH, BL), double-buffered
#define T_AH 0
#define T_AL 16384
#define T_BH 32768
#define T_BL 49152
#define STAGE 65536
#define SMEM_TOTAL (2 * STAGE)

// ---------------------------------------------------------------------------
__global__ void colsum_kernel(const float* __restrict__ adj, float* __restrict__ r) {
    __shared__ float red[4][64];
    const int jj = threadIdx.x, ii = threadIdx.y;
    const int col = blockIdx.x * 64 + jj;
    const int b = col / NN, j = col % NN;
    const float* a = adj + (size_t)b * NN * NN + j;
    float s = 0.f;
#pragma unroll 8
    for (int i = ii; i < NN; i += 4) s += a[(size_t)i * NN];
    red[ii][jj] = s;
    __syncthreads();
    if (ii == 0) {
        float t = red[0][jj] + red[1][jj] + red[2][jj] + red[3][jj];
        r[col] = (t > 0.f) ? rsqrtf(t) : 0.f;
    }
}

__global__ void transpose_split(const float* __restrict__ in,
                                __nv_bfloat16* __restrict__ ohi,
                                __nv_bfloat16* __restrict__ olo,
                                int R, int C) {
    __shared__ float t[32][33];
    const int i0 = blockIdx.x * 32, j0 = blockIdx.y * 32;
    const size_t zb = (size_t)blockIdx.z * R * C;
    const int tx = threadIdx.x, ty = threadIdx.y;
#pragma unroll
    for (int q = 0; q < 4; q++) {
        int j = j0 + ty + q * 8;
        t[ty + q * 8][tx] = in[zb + (size_t)j * C + i0 + tx];
    }
    __syncthreads();
#pragma unroll
    for (int q = 0; q < 4; q++) {
        int i = i0 + ty + q * 8;
        float v = t[tx][ty + q * 8];
        __nv_bfloat16 h = __float2bfloat16(v);
        __nv_bfloat16 l = __float2bfloat16(v - __bfloat162float(h));
        size_t o = zb + (size_t)i * R + j0 + tx;
        ohi[o] = h;
        olo[o] = l;
    }
}

__global__ void split_conv(const float* __restrict__ in,
                           __nv_bfloat16* __restrict__ hi,
                           __nv_bfloat16* __restrict__ lo, int n4) {
    int i = blockIdx.x * 256 + threadIdx.x;
    if (i >= n4) return;
    float4 v = ((const float4*)in)[i];
    float vv[4] = {v.x, v.y, v.z, v.w};
    __nv_bfloat16 h[4], l[4];
#pragma unroll
    for (int k = 0; k < 4; k++) {
        h[k] = __float2bfloat16(vv[k]);
        l[k] = __float2bfloat16(vv[k] - __bfloat162float(h[k]));
    }
    ((__nv_bfloat162*)hi)[i * 2 + 0] = __nv_bfloat162(h[0], h[1]);
    ((__nv_bfloat162*)hi)[i * 2 + 1] = __nv_bfloat162(h[2], h[3]);
    ((__nv_bfloat162*)lo)[i * 2 + 0] = __nv_bfloat162(l[0], l[1]);
    ((__nv_bfloat162*)lo)[i * 2 + 1] = __nv_bfloat162(l[2], l[3]);
}

// ---------------------------------------------------------------------------
// HMMA GEMM: D[128m x 128n] = sum_k A[m,k]*B[n,k]  (bf16 hi/lo x3, fp32 acc)
//   mode 0: out = r[n]*D          -> HsT hi/lo   (m=f, n=j)
//   mode 1: out = relu(r[m]*D+bias[n]) -> Xb hi/lo (m=i, n=f)
//   mode 2: out = r[m]*D+bias[n]       -> fp32    (m=i, n=f)
// ---------------------------------------------------------------------------
__global__ void __launch_bounds__(256, 1)
gcn_gemm(const __nv_bfloat16* __restrict__ Ahi, const __nv_bfloat16* __restrict__ Alo,
         const __nv_bfloat16* __restrict__ Bhi, const __nv_bfloat16* __restrict__ Blo,
         const float* __restrict__ r, const float* __restrict__ bias,
         int lda, size_t aBatch, int ldb, size_t bBatch, int nk, int mode,
         float* __restrict__ outF, __nv_bfloat16* __restrict__ oHi,
         __nv_bfloat16* __restrict__ oLo) {
    extern __shared__ char smem[];
    const uint32_t smb = smem_u32(smem);
    const int tid = threadIdx.x, lane = tid & 31, wid = tid >> 5;
    const int b = blockIdx.z;
    const int m0 = blockIdx.y * 128;
    const int n0 = blockIdx.x * 128;
    const int wr = wid & 1, wc = wid >> 1;      // 2x4 warp grid
    const int m0w = wr * 64, n0w = wc * 32;

    const __nv_bfloat16* aH = Ahi + b * aBatch + (size_t)m0 * lda;
    const __nv_bfloat16* aL = Alo + b * aBatch + (size_t)m0 * lda;
    const __nv_bfloat16* bH = Bhi + b * bBatch + (size_t)n0 * ldb;
    const __nv_bfloat16* bL = Blo + b * bBatch + (size_t)n0 * ldb;

    // per-thread cp.async slots: 4 iterations x (row, 16B chunk)
    int ldRow[4], ldC16[4];
#pragma unroll
    for (int i = 0; i < 4; i++) {
        int chunk = i * 256 + tid;         // 0..1023
        ldRow[i] = chunk >> 3;
        ldC16[i] = chunk & 7;
    }

    auto load_stage = [&](int kc, int buf) {
        const uint32_t sb = smb + buf * STAGE;
#pragma unroll
        for (int i = 0; i < 4; i++) {
            const int row = ldRow[i], c16 = ldC16[i];
            const uint32_t so = sw128((uint32_t)row * 128 + c16 * 16);
            const size_t ga = (size_t)row * lda + kc * 64 + c16 * 8;
            const size_t gb = (size_t)row * ldb + kc * 64 + c16 * 8;
            cp16(sb + T_AH + so, aH + ga);
            cp16(sb + T_AL + so, aL + ga);
            cp16(sb + T_BH + so, bH + gb);
            cp16(sb + T_BL + so, bL + gb);
        }
    };

    // ldmatrix per-thread base offsets (bytes, pre-swizzle)
    const uint32_t rowA = (uint32_t)(m0w + (lane & 15)) * 128 + (lane >> 4) * 16;
    const uint32_t rowB = (uint32_t)(n0w + ((lane >> 4) << 3) + (lane & 7)) * 128 +
                          ((lane >> 3) & 1) * 16;

    float acc[4][4][4];
#pragma unroll
    for (int a = 0; a < 4; a++)
#pragma unroll
        for (int c = 0; c < 4; c++)
#pragma unroll
            for (int d = 0; d < 4; d++) acc[a][c][d] = 0.f;

    load_stage(0, 0);
    CP_COMMIT();

    for (int s = 0; s < nk; s++) {
        if (s + 1 < nk) {
            load_stage(s + 1, (s + 1) & 1);
            CP_COMMIT();
            CP_WAIT1();
        } else {
            CP_WAIT0();
        }
        __syncthreads();

        const uint32_t sb = smb + (s & 1) * STAGE;
#pragma unroll
        for (int kt = 0; kt < 4; kt++) {
            uint32_t Ah[4][4], Al[4][4], Bh[2][4], Bl[2][4];
#pragma unroll
            for (int mi = 0; mi < 4; mi++) {
                const uint32_t off = sw128(rowA + mi * 2048 + kt * 32);
                ldsm4(Ah[mi], sb + T_AH + off);
                ldsm4(Al[mi], sb + T_AL + off);
            }
#pragma unroll
            for (int ni2 = 0; ni2 < 2; ni2++) {
                const uint32_t off = sw128(rowB + ni2 * 2048 + kt * 32);
                ldsm4(Bh[ni2], sb + T_BH + off);
                ldsm4(Bl[ni2], sb + T_BL + off);
            }
#pragma unroll
            for (int mi = 0; mi < 4; mi++)
#pragma unroll
                for (int ni = 0; ni < 4; ni++) {
                    const uint32_t* bh = &Bh[ni >> 1][(ni & 1) * 2];
                    const uint32_t* bl = &Bl[ni >> 1][(ni & 1) * 2];
                    mma_bf16(acc[mi][ni], Ah[mi], bh);
                    mma_bf16(acc[mi][ni], Ah[mi], bl);
                    mma_bf16(acc[mi][ni], Al[mi], bh);
                }
        }
        __syncthreads();
    }

    // ---------------- epilogue --------------------------------------------
    const int g = lane >> 2, cp2 = (lane & 3) * 2;
    const float* rr = r + b * NN;

    if (mode == 0) {
        // HsT[f][j] = r[j] * D ; f = m, j = n
#pragma unroll
        for (int mi = 0; mi < 4; mi++)
#pragma unroll
            for (int h = 0; h < 2; h++) {
                const int f = m0 + m0w + mi * 16 + g + h * 8;
                const size_t rowb = ((size_t)b * FF + f) * NN;
#pragma unroll
                for (int ni = 0; ni < 4; ni++) {
                    const int j = n0 + n0w + ni * 8 + cp2;
                    float v0 = acc[mi][ni][h * 2 + 0] * rr[j];
                    float v1 = acc[mi][ni][h * 2 + 1] * rr[j + 1];
                    __nv_bfloat16 h0 = __float2bfloat16(v0);
                    __nv_bfloat16 h1 = __float2bfloat16(v1);
                    __nv_bfloat16 l0 = __float2bfloat16(v0 - __bfloat162float(h0));
                    __nv_bfloat16 l1 = __float2bfloat16(v1 - __bfloat162float(h1));
                    *(__nv_bfloat162*)(oHi + rowb + j) = __nv_bfloat162(h0, h1);
                    *(__nv_bfloat162*)(oLo + rowb + j) = __nv_bfloat162(l0, l1);
                }
            }
    } else if (mode == 1) {
#pragma unroll
        for (int mi = 0; mi < 4; mi++)
#pragma unroll
            for (int h = 0; h < 2; h++) {
                const int i = m0 + m0w + mi * 16 + g + h * 8;
                const float sc = rr[i];
                const size_t rowb = ((size_t)b * NN + i) * FF;
#pragma unroll
                for (int ni = 0; ni < 4; ni++) {
                    const int f = n0 + n0w + ni * 8 + cp2;
                    float v0 = fmaxf(sc * acc[mi][ni][h * 2 + 0] + bias[f], 0.f);
                    float v1 = fmaxf(sc * acc[mi][ni][h * 2 + 1] + bias[f + 1], 0.f);
                    __nv_bfloat16 h0 = __float2bfloat16(v0);
                    __nv_bfloat16 h1 = __float2bfloat16(v1);
                    __nv_bfloat16 l0 = __float2bfloat16(v0 - __bfloat162float(h0));
                    __nv_bfloat16 l1 = __float2bfloat16(v1 - __bfloat162float(h1));
                    *(__nv_bfloat162*)(oHi + rowb + f) = __nv_bfloat162(h0, h1);
                    *(__nv_bfloat162*)(oLo + rowb + f) = __nv_bfloat162(l0, l1);
                }
            }
    } else {
#pragma unroll
        for (int mi = 0; mi < 4; mi++)
#pragma unroll
            for (int h = 0; h < 2; h++) {
                const int i = m0 + m0w + mi * 16 + g + h * 8;
                const float sc = rr[i];
                const size_t rowb = ((size_t)b * NN + i) * FF;
#pragma unroll
                for (int ni = 0; ni < 4; ni++) {
                    const int f = n0 + n0w + ni * 8 + cp2;
                    float2 v;
                    v.x = sc * acc[mi][ni][h * 2 + 0] + bias[f];
                    v.y = sc * acc[mi][ni][h * 2 + 1] + bias[f + 1];
                    *(float2*)(outF + rowb + f) = v;
                }
            }
    }
}

// ---------------------------------------------------------------------------
extern "C" void kernel_launch(void* const* d_in, const int* in_sizes, int n_in,
                              void* d_out, int out_size) {
    const float* X0  = (const float*)d_in[0];
    const float* adj = (const float*)d_in[1];
    const float* W1  = (const float*)d_in[2];
    const float* b1  = (const float*)d_in[3];
    const float* W2  = (const float*)d_in[4];
    const float* b2  = (const float*)d_in[5];
    const float* W3  = (const float*)d_in[6];
    const float* b3  = (const float*)d_in[7];
    float* out = (float*)d_out;

    float* r;
    __nv_bfloat16 *atH, *atL, *hsH, *hsL, *xbH, *xbL, *wtH, *wtL;
    cudaGetSymbolAddress((void**)&r,   g_r);
    cudaGetSymbolAddress((void**)&atH, g_adjT_hi);
    cudaGetSymbolAddress((void**)&atL, g_adjT_lo);
    cudaGetSymbolAddress((void**)&hsH, g_hst_hi);
    cudaGetSymbolAddress((void**)&hsL, g_hst_lo);
    cudaGetSymbolAddress((void**)&xbH, g_xb_hi);
    cudaGetSymbolAddress((void**)&xbL, g_xb_lo);
    cudaGetSymbolAddress((void**)&wtH, g_wt_hi);
    cudaGetSymbolAddress((void**)&wtL, g_wt_lo);

    cudaFuncSetAttribute(gcn_gemm, cudaFuncAttributeMaxDynamicSharedMemorySize,
                         SMEM_TOTAL);

    // prep
    colsum_kernel<<<BB * NN / 64, dim3(64, 4)>>>(adj, r);
    transpose_split<<<dim3(32, 32, BB), dim3(32, 8)>>>(adj, atH, atL, NN, NN);
    transpose_split<<<dim3(16, 16, 1), dim3(32, 8)>>>(W1, wtH, wtL, FF, FF);
    transpose_split<<<dim3(16, 16, 1), dim3(32, 8)>>>(W2, wtH + FF * FF,
                                                      wtL + FF * FF, FF, FF);
    transpose_split<<<dim3(16, 16, 1), dim3(32, 8)>>>(W3, wtH + 2 * FF * FF,
                                                      wtL + 2 * FF * FF, FF, FF);
    split_conv<<<BB * NN * FF / 4 / 256, 256>>>(X0, xbH, xbL, BB * NN * FF / 4);

    const dim3 g1(NN / 128, FF / 128, BB);   // GEMM1: HsT[f,j]  (8,4,16)
    const dim3 g2(FF / 128, NN / 128, BB);   // GEMM2: Y[i,f]    (4,8,16)
    const float* biases[3] = {b1, b2, b3};

    for (int l = 0; l < 3; l++) {
        // GEMM1: A = W^T [f][k] (lda=FF, no batch), B = Xb [j][k] (ldb=FF)
        gcn_gemm<<<g1, 256, SMEM_TOTAL>>>(
            wtH + l * FF * FF, wtL + l * FF * FF, xbH, xbL, r, (const float*)0,
            FF, (size_t)0, FF, (size_t)NN * FF, FF / 64, 0,
            (float*)0, hsH, hsL);
        // GEMM2: A = adjT [i][j] (lda=NN), B = HsT [f][j] (ldb=NN)
        const int mode = (l == 2) ? 2 : 1;
        gcn_gemm<<<g2, 256, SMEM_TOTAL>>>(
            atH, atL, hsH, hsL, r, biases[l],
            NN, (size_t)NN * NN, NN, (size_t)FF * NN, NN / 64, mode,
            out, xbH, xbL);
    }
}